// round 4
// baseline (speedup 1.0000x reference)
#include <cuda_runtime.h>

#define NN 100000
#define NE 1600000
#define NG 1000

// ---------------- scratch (device globals; zero-initialized at load) ----------------
__device__ float  d_h[NN * 64];
__device__ float  d_p[NN * 64];
__device__ float  d_u[NN * 64];
__device__ float  d_agg[NN * 64];
__device__ float  d_gpool[NG * 64];
__device__ int    d_gcnt[NG];
__device__ int    d_cnt[NN];          // zero-init; re-zeroed by k_scan1 each run
__device__ int    d_ptr[NN + 1];
__device__ int    d_cursor[NN];
__device__ int    d_srcS[NE];
__device__ float  d_attrS[NE * 16];   // attr rows permuted into CSR order
__device__ int    d_bsum[128];
__device__ float  d_C[3 * 16 * 64];
__device__ float  d_cv[3 * 64];
__device__ double d_stats[3 * 256];   // zero-init; re-zeroed by k_finalize each run
__device__ float  d_msc[3 * 64], d_msh[3 * 64];
__device__ float  d_usc[3 * 64], d_ush[3 * 64];

// ---------------- CSR build ----------------
__global__ void k_hist(const int* __restrict__ dst) {
    for (int i = blockIdx.x * blockDim.x + threadIdx.x; i < NE; i += gridDim.x * blockDim.x)
        atomicAdd(&d_cnt[dst[i]], 1);
}

__global__ __launch_bounds__(1024) void k_scan1() {
    __shared__ int ws[32];
    int t = threadIdx.x;
    int i = blockIdx.x * 1024 + t;
    int v = 0;
    if (i < NN) { v = d_cnt[i]; d_cnt[i] = 0; }   // self-clean for next run
    int x = v;
#pragma unroll
    for (int off = 1; off < 32; off <<= 1) {
        int y = __shfl_up_sync(0xffffffffu, x, off);
        if ((t & 31) >= off) x += y;
    }
    if ((t & 31) == 31) ws[t >> 5] = x;
    __syncthreads();
    if (t < 32) {
        int y = ws[t]; int z = y;
#pragma unroll
        for (int off = 1; off < 32; off <<= 1) {
            int w = __shfl_up_sync(0xffffffffu, z, off);
            if (t >= off) z += w;
        }
        ws[t] = z - y;
    }
    __syncthreads();
    int excl = x - v + ws[t >> 5];
    if (i < NN) d_ptr[i] = excl;
    if (t == 1023) d_bsum[blockIdx.x] = excl + v;
}

// fused scan2+scan3: per-256-block the bsum prefix index is constant (blockIdx>>2)
__global__ void k_scanF() {
    __shared__ int sP;
    int t = threadIdx.x;
    int pre = blockIdx.x >> 2;
    if (t < 32) {
        int acc = 0;
        for (int idx = t; idx < pre; idx += 32) acc += d_bsum[idx];
#pragma unroll
        for (int off = 16; off >= 1; off >>= 1) acc += __shfl_down_sync(0xffffffffu, acc, off);
        if (t == 0) sP = acc;
    }
    __syncthreads();
    int i = blockIdx.x * 256 + t;
    if (i < NN) {
        int val = d_ptr[i] + sP;
        d_ptr[i] = val;
        d_cursor[i] = val;
    }
    if (blockIdx.x == 0 && t == 0) d_ptr[NN] = NE;
}

// fused: scatter (CSR fill + attr permute) | embed | composite
#define SC_BLOCKS 2048
#define EM_BLOCKS 512
__global__ __launch_bounds__(256) void k_setup(const int* __restrict__ src,
                                               const int* __restrict__ dst,
                                               const float* __restrict__ attr,
                                               const float* __restrict__ x,
                                               const float* __restrict__ node_W,
                                               const float* __restrict__ node_b,
                                               const float* __restrict__ edge_W,
                                               const float* __restrict__ edge_b,
                                               const float* __restrict__ msg_W,
                                               const float* __restrict__ msg_b) {
    int b = blockIdx.x;
    if (b < SC_BLOCKS) {
        // scatter + attr permute
        const float4* a4 = (const float4*)attr;
        float4* s4 = (float4*)d_attrS;
        for (int i = b * 256 + threadIdx.x; i < NE; i += SC_BLOCKS * 256) {
            int pos = atomicAdd(&d_cursor[dst[i]], 1);
            d_srcS[pos] = src[i];
            float4 v0 = a4[i * 4 + 0], v1 = a4[i * 4 + 1], v2 = a4[i * 4 + 2], v3 = a4[i * 4 + 3];
            s4[pos * 4 + 0] = v0; s4[pos * 4 + 1] = v1; s4[pos * 4 + 2] = v2; s4[pos * 4 + 3] = v3;
        }
    } else if (b < SC_BLOCKS + EM_BLOCKS) {
        // embed: h0 = x @ node_W + node_b (warp per node)
        int lane = threadIdx.x & 31;
        float w0[32], w1[32];
#pragma unroll
        for (int k = 0; k < 32; k++) { w0[k] = node_W[k * 64 + lane]; w1[k] = node_W[k * 64 + lane + 32]; }
        float b0 = node_b[lane], b1 = node_b[lane + 32];
        int gw = ((b - SC_BLOCKS) * 256 + threadIdx.x) >> 5;
        int nw = (EM_BLOCKS * 256) >> 5;
        for (int n = gw; n < NN; n += nw) {
            float xv = x[n * 32 + lane];
            float a0 = b0, a1 = b1;
#pragma unroll
            for (int k = 0; k < 32; k++) {
                float bc = __shfl_sync(0xffffffffu, xv, k);
                a0 = fmaf(bc, w0[k], a0); a1 = fmaf(bc, w1[k], a1);
            }
            d_h[n * 64 + lane] = a0; d_h[n * 64 + lane + 32] = a1;
        }
    } else {
        // composite: C_l = edge_W @ msg_W[l][64:96,:]; cv_l = edge_b@.. + msg_b
        int t = threadIdx.x;
        if (t < 192) {
            int l = t >> 6, f = t & 63;
            const float* Wm = msg_W + l * 96 * 64 + 64 * 64;
            for (int kk = 0; kk < 16; kk++) {
                float s = 0.f;
                for (int j = 0; j < 32; j++) s = fmaf(edge_W[kk * 32 + j], Wm[j * 64 + f], s);
                d_C[l * 1024 + kk * 64 + f] = s;
            }
            float cv = msg_b[l * 64 + f];
            for (int j = 0; j < 32; j++) cv = fmaf(edge_b[j], Wm[j * 64 + f], cv);
            d_cv[l * 64 + f] = cv;
        }
    }
}

// p = in @ msg_W[l][0:64,:] with previous-layer BN affine folded into weights
__global__ __launch_bounds__(256) void k_p(const float* __restrict__ msg_W, int l) {
    const float* W = msg_W + l * 96 * 64;
    const float* in = (l == 0) ? d_h : d_u;
    const float* sc = d_usc + (l - 1) * 64;
    const float* shv = d_ush + (l - 1) * 64;
    int lane = threadIdx.x & 31;
    int half = (threadIdx.x >> 5) & 1;
    int pib  = threadIdx.x >> 6;
    float w0[32], w1[32];
    float bias0 = 0.f, bias1 = 0.f;
#pragma unroll
    for (int kk = 0; kk < 32; kk++) {
        int k = half * 32 + kk;
        float wa = W[k * 64 + lane], wb = W[k * 64 + lane + 32];
        if (l > 0) {
            bias0 = fmaf(shv[k], wa, bias0); bias1 = fmaf(shv[k], wb, bias1);
            float s = sc[k]; wa *= s; wb *= s;
        }
        w0[kk] = wa; w1[kk] = wb;
    }
    __shared__ float2 red[4][32];
    int stride = gridDim.x * 4;
    for (int nb = blockIdx.x * 4; nb < NN; nb += stride) {
        int n = nb + pib;
        bool act = (n < NN);
        float a0 = bias0, a1 = bias1;
        if (act) {
            float hv = in[n * 64 + half * 32 + lane];
#pragma unroll
            for (int kk = 0; kk < 32; kk++) {
                float bc = __shfl_sync(0xffffffffu, hv, kk);
                a0 = fmaf(bc, w0[kk], a0); a1 = fmaf(bc, w1[kk], a1);
            }
        }
        if (half == 1) red[pib][lane] = make_float2(a0, a1);
        __syncthreads();
        if (act && half == 0) {
            float2 o = red[pib][lane];
            d_p[n * 64 + lane]      = a0 + o.x;
            d_p[n * 64 + lane + 32] = a1 + o.y;
        }
        __syncthreads();
    }
}

// HOT: warp per dst node; m = relu(p[src] + attrS[j]@C + cv); raw agg + BN stats.
// attrS is CSR-ordered -> sequential; no shuffles (broadcast LDG of attr row).
__global__ __launch_bounds__(256) void k_edge(int l) {
    int lane = threadIdx.x & 31;
    const float* C = d_C + l * 1024;
    float cw0[16], cw1[16];
#pragma unroll
    for (int k = 0; k < 16; k++) { cw0[k] = C[k * 64 + lane]; cw1[k] = C[k * 64 + lane + 32]; }
    float cb0 = d_cv[l * 64 + lane], cb1 = d_cv[l * 64 + lane + 32];
    float s0 = 0.f, q0 = 0.f, s1 = 0.f, q1 = 0.f;
    int gw = (blockIdx.x * blockDim.x + threadIdx.x) >> 5;
    int nw = (gridDim.x * blockDim.x) >> 5;
    for (int n = gw; n < NN; n += nw) {
        int beg = __ldg(&d_ptr[n]), end = __ldg(&d_ptr[n + 1]);
        float a0 = 0.f, a1 = 0.f;
        for (int j = beg; j < end; j++) {
            int srcn = __ldg(&d_srcS[j]);
            const float4* ap = (const float4*)(d_attrS + (size_t)j * 16);
            float4 x0 = __ldg(ap), x1 = __ldg(ap + 1), x2 = __ldg(ap + 2), x3 = __ldg(ap + 3);
            const float* pr = d_p + srcn * 64;
            float pv0 = __ldg(&pr[lane]), pv1 = __ldg(&pr[lane + 32]);
            float m0 = pv0 + cb0, m1 = pv1 + cb1;
            m0 = fmaf(x0.x, cw0[0], m0);  m1 = fmaf(x0.x, cw1[0], m1);
            m0 = fmaf(x0.y, cw0[1], m0);  m1 = fmaf(x0.y, cw1[1], m1);
            m0 = fmaf(x0.z, cw0[2], m0);  m1 = fmaf(x0.z, cw1[2], m1);
            m0 = fmaf(x0.w, cw0[3], m0);  m1 = fmaf(x0.w, cw1[3], m1);
            m0 = fmaf(x1.x, cw0[4], m0);  m1 = fmaf(x1.x, cw1[4], m1);
            m0 = fmaf(x1.y, cw0[5], m0);  m1 = fmaf(x1.y, cw1[5], m1);
            m0 = fmaf(x1.z, cw0[6], m0);  m1 = fmaf(x1.z, cw1[6], m1);
            m0 = fmaf(x1.w, cw0[7], m0);  m1 = fmaf(x1.w, cw1[7], m1);
            m0 = fmaf(x2.x, cw0[8], m0);  m1 = fmaf(x2.x, cw1[8], m1);
            m0 = fmaf(x2.y, cw0[9], m0);  m1 = fmaf(x2.y, cw1[9], m1);
            m0 = fmaf(x2.z, cw0[10], m0); m1 = fmaf(x2.z, cw1[10], m1);
            m0 = fmaf(x2.w, cw0[11], m0); m1 = fmaf(x2.w, cw1[11], m1);
            m0 = fmaf(x3.x, cw0[12], m0); m1 = fmaf(x3.x, cw1[12], m1);
            m0 = fmaf(x3.y, cw0[13], m0); m1 = fmaf(x3.y, cw1[13], m1);
            m0 = fmaf(x3.z, cw0[14], m0); m1 = fmaf(x3.z, cw1[14], m1);
            m0 = fmaf(x3.w, cw0[15], m0); m1 = fmaf(x3.w, cw1[15], m1);
            m0 = fmaxf(m0, 0.f); m1 = fmaxf(m1, 0.f);
            a0 += m0; a1 += m1;
            s0 += m0; q0 = fmaf(m0, m0, q0);
            s1 += m1; q1 = fmaf(m1, m1, q1);
        }
        d_agg[n * 64 + lane]      = a0;
        d_agg[n * 64 + lane + 32] = a1;
    }
    __shared__ float sS[64], sQ[64];
    int t = threadIdx.x;
    if (t < 64) { sS[t] = 0.f; sQ[t] = 0.f; }
    __syncthreads();
    atomicAdd(&sS[lane], s0);      atomicAdd(&sS[lane + 32], s1);
    atomicAdd(&sQ[lane], q0);      atomicAdd(&sQ[lane + 32], q1);
    __syncthreads();
    double* st = d_stats + l * 256;
    if (t < 64) { atomicAdd(&st[t], (double)sS[t]); atomicAdd(&st[64 + t], (double)sQ[t]); }
}

__global__ void k_finalize(int l, int which, const float* __restrict__ gamma,
                           const float* __restrict__ beta, float invC) {
    int f = threadIdx.x;
    double* st = d_stats + l * 256 + (which ? 128 : 0);
    double mu  = st[f] * (double)invC;
    double var = st[64 + f] * (double)invC - mu * mu;
    st[f] = 0.0; st[64 + f] = 0.0;   // self-clean for next run
    float sc = gamma[f] * rsqrtf((float)var + 1e-5f);
    float sh = beta[f] - (float)mu * sc;
    if (which == 0) { d_msc[l * 64 + f] = sc; d_msh[l * 64 + f] = sh; }
    else            { d_usc[l * 64 + f] = sc; d_ush[l * 64 + f] = sh; }
}

// u = relu( affine(h) @ Wu_h + affine(agg) @ Wu_a + b ); BN affines folded into weights
__global__ __launch_bounds__(256) void k_update(const float* __restrict__ upd_W,
                                                const float* __restrict__ upd_b, int l) {
    const float* W = upd_W + l * 128 * 64;
    const float* in = (l == 0) ? d_h : d_u;
    const float* psc = d_usc + (l - 1) * 64;
    const float* psh = d_ush + (l - 1) * 64;
    const float* msc = d_msc + l * 64;
    const float* msh = d_msh + l * 64;
    int lane = threadIdx.x & 31;
    int sub  = (threadIdx.x >> 5) & 3;
    int slot = threadIdx.x >> 7;
    float w0[32], w1[32];
    float bias0 = 0.f, bias1 = 0.f;
#pragma unroll
    for (int kk = 0; kk < 32; kk++) {
        int k = sub * 32 + kk;
        float wa = W[k * 64 + lane], wb = W[k * 64 + lane + 32];
        if (sub < 2) {
            if (l > 0) {
                bias0 = fmaf(psh[k], wa, bias0); bias1 = fmaf(psh[k], wb, bias1);
                float s = psc[k]; wa *= s; wb *= s;
            }
        } else {
            int ka = k - 64;
            bias0 = fmaf(msh[ka], wa, bias0); bias1 = fmaf(msh[ka], wb, bias1);  // ×deg later
            float s = msc[ka]; wa *= s; wb *= s;
        }
        w0[kk] = wa; w1[kk] = wb;
    }
    float b0 = upd_b[l * 64 + lane], b1 = upd_b[l * 64 + lane + 32];
    __shared__ float2 red[2][4][32];
    float s0 = 0.f, q0 = 0.f, s1 = 0.f, q1 = 0.f;
    int stride = gridDim.x * 2;
    for (int nb = blockIdx.x * 2; nb < NN; nb += stride) {
        int n = nb + slot;
        bool act = (n < NN);
        float a0, a1;
        if (sub < 2) { a0 = bias0; a1 = bias1; }
        else {
            float degf = act ? (float)(__ldg(&d_ptr[n + 1]) - __ldg(&d_ptr[n])) : 0.f;
            a0 = degf * bias0; a1 = degf * bias1;
        }
        if (act) {
            float iv = (sub < 2) ? in[n * 64 + sub * 32 + lane]
                                 : d_agg[n * 64 + (sub - 2) * 32 + lane];
#pragma unroll
            for (int kk = 0; kk < 32; kk++) {
                float bc = __shfl_sync(0xffffffffu, iv, kk);
                a0 = fmaf(bc, w0[kk], a0); a1 = fmaf(bc, w1[kk], a1);
            }
        }
        if (sub) red[slot][sub][lane] = make_float2(a0, a1);
        __syncthreads();
        if (act && sub == 0) {
            float2 r1 = red[slot][1][lane], r2 = red[slot][2][lane], r3 = red[slot][3][lane];
            float v0 = a0 + r1.x + r2.x + r3.x + b0;
            float v1 = a1 + r1.y + r2.y + r3.y + b1;
            v0 = fmaxf(v0, 0.f); v1 = fmaxf(v1, 0.f);
            d_u[n * 64 + lane]      = v0;
            d_u[n * 64 + lane + 32] = v1;
            s0 += v0; q0 = fmaf(v0, v0, q0);
            s1 += v1; q1 = fmaf(v1, v1, q1);
        }
        __syncthreads();
    }
    __shared__ float sS[64], sQ[64];
    int t = threadIdx.x;
    if (t < 64) { sS[t] = 0.f; sQ[t] = 0.f; }
    __syncthreads();
    if (sub == 0) {
        atomicAdd(&sS[lane], s0);      atomicAdd(&sS[lane + 32], s1);
        atomicAdd(&sQ[lane], q0);      atomicAdd(&sQ[lane + 32], q1);
    }
    __syncthreads();
    double* st = d_stats + l * 256 + 128;
    if (t < 64) { atomicAdd(&st[t], (double)sS[t]); atomicAdd(&st[64 + t], (double)sQ[t]); }
}

// segmented pool over sorted batch; accumulates raw u + node counts
#define PL_BLOCKS 128
__global__ __launch_bounds__(256) void k_pool(const int* __restrict__ batch) {
    int lane = threadIdx.x & 31;
    int w = (blockIdx.x * 256 + threadIdx.x) >> 5;      // 1024 warps
    const int chunk = (NN + 1023) / 1024;               // 98
    int s = w * chunk, e = s + chunk;
    if (e > NN) e = NN;
    if (s >= NN) return;
    int curg = __ldg(&batch[s]);
    float A0 = 0.f, A1 = 0.f; int cnt = 0;
    for (int n = s; n < e; n++) {
        int g = __ldg(&batch[n]);
        if (g != curg) {
            atomicAdd(&d_gpool[curg * 64 + lane],      A0);
            atomicAdd(&d_gpool[curg * 64 + lane + 32], A1);
            if (lane == 0) atomicAdd(&d_gcnt[curg], cnt);
            curg = g; A0 = 0.f; A1 = 0.f; cnt = 0;
        }
        A0 += d_u[n * 64 + lane];
        A1 += d_u[n * 64 + lane + 32];
        cnt++;
    }
    atomicAdd(&d_gpool[curg * 64 + lane],      A0);
    atomicAdd(&d_gpool[curg * 64 + lane + 32], A1);
    if (lane == 0) atomicAdd(&d_gcnt[curg], cnt);
}

// readout with final BN affine folded: g = usc2*pool + cnt*ush2; self-cleans pool/cnt
__global__ void k_readout(const float* __restrict__ r1_W, const float* __restrict__ r1_b,
                          const float* __restrict__ r2_W, const float* __restrict__ r2_b,
                          float* __restrict__ out) {
    int gid = blockIdx.x, f = threadIdx.x;
    __shared__ float gv[64];
    float cntf = (float)d_gcnt[gid];
    gv[f] = fmaf(d_usc[2 * 64 + f], d_gpool[gid * 64 + f], cntf * d_ush[2 * 64 + f]);
    __syncthreads();
    // self-clean after read
    d_gpool[gid * 64 + f] = 0.f;
    if (f == 0) d_gcnt[gid] = 0;
    float acc = r1_b[f];
    for (int k = 0; k < 64; k++)
        acc = fmaf(gv[k], r1_W[k * 64 + f], acc);
    acc = fmaxf(acc, 0.f);
    float val = acc * r2_W[f];
    __shared__ float sh[64];
    sh[f] = val;
    __syncthreads();
    if (f < 32) sh[f] += sh[f + 32];
    __syncthreads();
    if (f < 16) sh[f] += sh[f + 16];
    __syncthreads();
    if (f < 8) sh[f] += sh[f + 8];
    __syncthreads();
    if (f < 4) sh[f] += sh[f + 4];
    __syncthreads();
    if (f < 2) sh[f] += sh[f + 2];
    __syncthreads();
    if (f == 0) out[gid] = sh[0] + sh[1] + r2_b[0];
}

extern "C" void kernel_launch(void* const* d_in, const int* in_sizes, int n_in,
                              void* d_out, int out_size) {
    const float* x         = (const float*)d_in[0];
    const float* edge_attr = (const float*)d_in[1];
    const int*   edge_idx  = (const int*)d_in[2];
    const int*   batch     = (const int*)d_in[3];
    const float* node_W    = (const float*)d_in[4];
    const float* node_b    = (const float*)d_in[5];
    const float* edge_W    = (const float*)d_in[6];
    const float* edge_b    = (const float*)d_in[7];
    const float* msg_W     = (const float*)d_in[8];
    const float* msg_b     = (const float*)d_in[9];
    const float* msg_gamma = (const float*)d_in[10];
    const float* msg_beta  = (const float*)d_in[11];
    const float* upd_W     = (const float*)d_in[12];
    const float* upd_b     = (const float*)d_in[13];
    const float* upd_gamma = (const float*)d_in[14];
    const float* upd_beta  = (const float*)d_in[15];
    const float* r1_W      = (const float*)d_in[16];
    const float* r1_b      = (const float*)d_in[17];
    const float* r2_W      = (const float*)d_in[18];
    const float* r2_b      = (const float*)d_in[19];
    float* out = (float*)d_out;

    const int* src = edge_idx;
    const int* dst = edge_idx + NE;

    k_hist<<<1024, 256>>>(dst);                                   // 0
    int nb = (NN + 1023) / 1024;
    k_scan1<<<nb, 1024>>>();                                      // 1
    k_scanF<<<(NN + 255) / 256, 256>>>();                         // 2
    k_setup<<<SC_BLOCKS + EM_BLOCKS + 1, 256>>>(src, dst, edge_attr, x, node_W, node_b,
                                                edge_W, edge_b, msg_W, msg_b);  // 3
    for (int l = 0; l < 3; l++) {
        k_p<<<1024, 256>>>(msg_W, l);                             // 4 (l=0)
        k_edge<<<2048, 256>>>(l);                                 // 5 (l=0)  <- ncu -s 5 target
        k_finalize<<<1, 64>>>(l, 0, msg_gamma + l * 64, msg_beta + l * 64, 1.0f / NE);
        k_update<<<1024, 256>>>(upd_W, upd_b, l);
        k_finalize<<<1, 64>>>(l, 1, upd_gamma + l * 64, upd_beta + l * 64, 1.0f / NN);
    }
    k_pool<<<PL_BLOCKS, 256>>>(batch);
    k_readout<<<NG, 64>>>(r1_W, r1_b, r2_W, r2_b, out);
}